// round 6
// baseline (speedup 1.0000x reference)
#include <cuda_runtime.h>
#include <math.h>
#include <float.h>

// RepulsionLoss: B=8, N=4096, KNN=4, H=0.03
// Batched branch-free top-5 (6 alu ops/pair: sort-4 + bitonic min + merge-5).
// No smem staging: candidates (64 KB/batch, augmented float4) are L1-resident;
// each thread streams them via __ldg with a mirror-broadcast pattern.
// v = |p|^2 - 2 p.q (|q|^2 deferred); self is the strict global min -> slot 0
// after the final merge, dropped (ref: top_k(KNN+1)-drop-first).

#define B_SZ     8
#define N_SZ     4096
#define THREADS  128
#define SLOTS    8                     // query-pair slots per block
#define SPLIT    16                    // candidate splits per query
#define QPB      (SLOTS * 2)           // 16 queries per block
#define NBATCH   (N_SZ / SPLIT / 4)    // 64 batches of 4 per thread
#define GROUPS   (N_SZ / QPB)          // 256
#define GRID_SZ  (B_SZ * GROUPS)       // 2048 blocks
#define H2       (0.03f * 0.03f)
#define FULL     0xffffffffu

__device__ float4 g_aug[B_SZ * N_SZ];      // (x, y, z, |p|^2)
__device__ float  g_partial[GRID_SZ];
__device__ int    g_done;                   // zero-init; self-resetting

#define CE(x, y) { float t_ = fminf((x), (y)); (y) = fmaxf((x), (y)); (x) = t_; }

// Classic 9-op insert (rare merge phases only).
__device__ __forceinline__ void ins5(float& d0, float& d1, float& d2,
                                     float& d3, float& d4, float v) {
    d4 = fminf(d4, v);
    CE(d3, d4) CE(d2, d3) CE(d1, d2) CE(d0, d1)
}

__global__ __launch_bounds__(256)
void augment_kernel(const float* __restrict__ pc) {
    int i = blockIdx.x * 256 + threadIdx.x;
    float x = pc[i * 3 + 0];
    float y = pc[i * 3 + 1];
    float z = pc[i * 3 + 2];
    g_aug[i] = make_float4(x, y, z, fmaf(x, x, fmaf(y, y, z * z)));
}

__global__ __launch_bounds__(THREADS)
void repulsion_knn_kernel(const float* __restrict__ pc, float* __restrict__ out) {
    __shared__ float mbufA[THREADS][5];
    __shared__ float mbufB[THREADS][5];
    __shared__ float wsum[SLOTS];
    __shared__ int   is_last;

    const int tid   = threadIdx.x;
    const int split = tid & (SPLIT - 1);
    const int slot  = tid >> 4;                   // 0..7
    const int b     = blockIdx.x >> 8;            // / GROUPS
    const int grp   = blockIdx.x & (GROUPS - 1);
    const int qa    = grp * QPB + slot * 2;
    const int qb    = qa + 1;

    const float*  __restrict__ batch = pc + (size_t)b * N_SZ * 3;
    const float4* __restrict__ cand  = g_aug + b * N_SZ + split;

    const float axm = -2.0f * batch[qa * 3 + 0];
    const float aym = -2.0f * batch[qa * 3 + 1];
    const float azm = -2.0f * batch[qa * 3 + 2];
    const float bxm = -2.0f * batch[qb * 3 + 0];
    const float bym = -2.0f * batch[qb * 3 + 1];
    const float bzm = -2.0f * batch[qb * 3 + 2];
    const float aqs = 0.25f * fmaf(axm, axm, fmaf(aym, aym, azm * azm));
    const float bqs = 0.25f * fmaf(bxm, bxm, fmaf(bym, bym, bzm * bzm));

    float a0 = FLT_MAX, a1 = FLT_MAX, a2 = FLT_MAX, a3 = FLT_MAX, a4 = FLT_MAX;
    float b0 = FLT_MAX, b1 = FLT_MAX, b2 = FLT_MAX, b3 = FLT_MAX, b4 = FLT_MAX;

    // Lanes l and l+16 read identical addresses (broadcast); lanes 0-15 read
    // 16 contiguous float4s. All of g_aug[batch] (64 KB) stays L1-resident.
    #pragma unroll 4
    for (int k = 0; k < NBATCH; ++k) {
        float4 p0 = __ldg(&cand[(k * 4 + 0) * SPLIT]);
        float4 p1 = __ldg(&cand[(k * 4 + 1) * SPLIT]);
        float4 p2 = __ldg(&cand[(k * 4 + 2) * SPLIT]);
        float4 p3 = __ldg(&cand[(k * 4 + 3) * SPLIT]);

        // ---- query A ----
        {
            float va = fmaf(p0.x, axm, fmaf(p0.y, aym, fmaf(p0.z, azm, p0.w)));
            float vb = fmaf(p1.x, axm, fmaf(p1.y, aym, fmaf(p1.z, azm, p1.w)));
            float vc = fmaf(p2.x, axm, fmaf(p2.y, aym, fmaf(p2.z, azm, p2.w)));
            float vd = fmaf(p3.x, axm, fmaf(p3.y, aym, fmaf(p3.z, azm, p3.w)));
            CE(va, vb) CE(vc, vd) CE(va, vc) CE(vb, vd) CE(vb, vc)
            a1 = fminf(a1, vd); a2 = fminf(a2, vc);
            a3 = fminf(a3, vb); a4 = fminf(a4, va);
            CE(a0, a4) CE(a1, a3) CE(a2, a4) CE(a1, a2) CE(a3, a4)
        }
        // ---- query B ----
        {
            float va = fmaf(p0.x, bxm, fmaf(p0.y, bym, fmaf(p0.z, bzm, p0.w)));
            float vb = fmaf(p1.x, bxm, fmaf(p1.y, bym, fmaf(p1.z, bzm, p1.w)));
            float vc = fmaf(p2.x, bxm, fmaf(p2.y, bym, fmaf(p2.z, bzm, p2.w)));
            float vd = fmaf(p3.x, bxm, fmaf(p3.y, bym, fmaf(p3.z, bzm, p3.w)));
            CE(va, vb) CE(vc, vd) CE(va, vc) CE(vb, vd) CE(vb, vc)
            b1 = fminf(b1, vd); b2 = fminf(b2, vc);
            b3 = fminf(b3, vb); b4 = fminf(b4, va);
            CE(b0, b4) CE(b1, b3) CE(b2, b4) CE(b1, b2) CE(b3, b4)
        }
    }

    // Tree-merge the 16 per-split lists of each query.
    mbufA[tid][0] = a0; mbufA[tid][1] = a1; mbufA[tid][2] = a2;
    mbufA[tid][3] = a3; mbufA[tid][4] = a4;
    mbufB[tid][0] = b0; mbufB[tid][1] = b1; mbufB[tid][2] = b2;
    mbufB[tid][3] = b3; mbufB[tid][4] = b4;

    #pragma unroll
    for (int step = SPLIT / 2; step >= 1; step >>= 1) {
        __syncthreads();
        if (split < step) {
            const float* oa = mbufA[tid + step];
            const float* ob = mbufB[tid + step];
            #pragma unroll
            for (int k = 0; k < 5; ++k) {
                ins5(a0, a1, a2, a3, a4, oa[k]);
                ins5(b0, b1, b2, b3, b4, ob[k]);
            }
            mbufA[tid][0] = a0; mbufA[tid][1] = a1; mbufA[tid][2] = a2;
            mbufA[tid][3] = a3; mbufA[tid][4] = a4;
            mbufB[tid][0] = b0; mbufB[tid][1] = b1; mbufB[tid][2] = b2;
            mbufB[tid][3] = b3; mbufB[tid][4] = b4;
        }
    }
    __syncthreads();

    if (split == 0) {
        const float inv = -1.0f / H2;
        float acc = 0.0f;
        float s;
        s = fmaxf(a1 + aqs, 0.0f); acc -= s * expf(s * inv);
        s = fmaxf(a2 + aqs, 0.0f); acc -= s * expf(s * inv);
        s = fmaxf(a3 + aqs, 0.0f); acc -= s * expf(s * inv);
        s = fmaxf(a4 + aqs, 0.0f); acc -= s * expf(s * inv);
        s = fmaxf(b1 + bqs, 0.0f); acc -= s * expf(s * inv);
        s = fmaxf(b2 + bqs, 0.0f); acc -= s * expf(s * inv);
        s = fmaxf(b3 + bqs, 0.0f); acc -= s * expf(s * inv);
        s = fmaxf(b4 + bqs, 0.0f); acc -= s * expf(s * inv);
        wsum[slot] = acc;
    }
    __syncthreads();

    if (tid == 0) {
        float sacc = 0.0f;
        #pragma unroll
        for (int w = 0; w < SLOTS; ++w) sacc += wsum[w];
        g_partial[blockIdx.x] = sacc;
        __threadfence();
        int n = atomicAdd(&g_done, 1);
        is_last = (n == GRID_SZ - 1);
    }
    __syncthreads();

    if (is_last) {
        __threadfence();
        float v = 0.0f;
        #pragma unroll
        for (int i = tid; i < GRID_SZ; i += THREADS) v += g_partial[i];
        #pragma unroll
        for (int o = 16; o > 0; o >>= 1)
            v += __shfl_down_sync(FULL, v, o);
        __shared__ float fsum[THREADS / 32];
        if ((tid & 31) == 0) fsum[tid >> 5] = v;
        __syncthreads();
        if (tid == 0) {
            out[0] = fsum[0] + fsum[1] + fsum[2] + fsum[3];
            g_done = 0;                       // reset for next graph replay
        }
    }
}

extern "C" void kernel_launch(void* const* d_in, const int* in_sizes, int n_in,
                              void* d_out, int out_size) {
    const float* pc = (const float*)d_in[0];
    augment_kernel<<<(B_SZ * N_SZ) / 256, 256>>>(pc);
    repulsion_knn_kernel<<<GRID_SZ, THREADS>>>(pc, (float*)d_out);
}

// round 7
// speedup vs baseline: 1.3584x; 1.3584x over previous
#include <cuda_runtime.h>
#include <math.h>
#include <float.h>

// RepulsionLoss: B=8, N=4096, KNN=4, H=0.03
// Spatial pruning: exp(-d/H^2) makes neighbors with d^2 >= 0.0225 contribute
// <= 3e-13 each (<= 2e-7 total). Bucket points by x (width 0.15), stable
// counting sort, and scan only buckets [b-1, b+1] per query: every neighbor
// with |dx| < 0.15 is provably inside the window. ~520 candidates/query vs
// 4096. Selection: batched branch-free top-5 (sort-4 + bitonic min + merge-5),
// 2 splits/query merged via shfl. Self is the global min -> slot 0, dropped
// (matches reference top_k(KNN+1)-drop-first). Fully deterministic (no
// data-dependent atomics; stable sort).

#define B_SZ     8
#define N_SZ     4096
#define NB       80
#define WID      0.15f
#define X0       (-6.0f)
#define INVW     (1.0f / WID)
#define H2       (0.03f * 0.03f)
#define FULL     0xffffffffu

#define MTHREADS 256
#define MGRID    ((B_SZ * N_SZ * 2) / MTHREADS)   // 256 blocks, 2 splits/query

__device__ float4 g_sorted[B_SZ * N_SZ + 4];      // (x,y,z,|p|^2), +pad for over-read
__device__ int    g_sbucket[B_SZ * N_SZ];
__device__ int    g_bstart[B_SZ * (NB + 1)];
__device__ float  g_partial[MGRID];
__device__ int    g_done;                          // zero-init; self-resetting

#define CE(x, y) { float t_ = fminf((x), (y)); (y) = fmaxf((x), (y)); (x) = t_; }

__device__ __forceinline__ void ins5(float& d0, float& d1, float& d2,
                                     float& d3, float& d4, float v) {
    d4 = fminf(d4, v);
    CE(d3, d4) CE(d2, d3) CE(d1, d2) CE(d0, d1)
}

// ---------------- build: stable counting sort by x-bucket -------------------
__global__ __launch_bounds__(1024)
void build_kernel(const float* __restrict__ pc) {
    __shared__ int hist[NB][128];      // [bucket][pass*32 + warp]
    __shared__ int btot[NB];
    __shared__ int bstart[NB + 1];

    const int tid  = threadIdx.x;
    const int bt   = blockIdx.x;       // batch
    const int warp = tid >> 5;
    const int lane = tid & 31;

    for (int i = tid; i < NB * 128; i += 1024)
        (&hist[0][0])[i] = 0;
    __syncthreads();

    float xs[4], ys[4], zs[4];
    int   bs[4], lr[4];
    #pragma unroll
    for (int p = 0; p < 4; ++p) {
        int i = p * 1024 + tid;
        const float* src = pc + ((size_t)bt * N_SZ + i) * 3;
        float x = src[0], y = src[1], z = src[2];
        int b = (int)((x - X0) * INVW);
        b = max(0, min(NB - 1, b));
        unsigned m = __match_any_sync(FULL, b);
        lr[p] = __popc(m & ((1u << lane) - 1u));
        if ((__ffs(m) - 1) == lane) hist[b][p * 32 + warp] = __popc(m);
        xs[p] = x; ys[p] = y; zs[p] = z; bs[p] = b;
    }
    __syncthreads();

    if (tid < NB) {                    // exclusive scan over the 128 warp-slots
        int acc = 0;
        for (int s = 0; s < 128; ++s) {
            int c = hist[tid][s];
            hist[tid][s] = acc;
            acc += c;
        }
        btot[tid] = acc;
    }
    __syncthreads();
    if (tid == 0) {                    // exclusive scan over buckets
        int a = 0;
        for (int b = 0; b < NB; ++b) { bstart[b] = a; a += btot[b]; }
        bstart[NB] = a;                // == N_SZ
    }
    __syncthreads();

    if (tid <= NB) g_bstart[bt * (NB + 1) + tid] = bstart[tid];

    #pragma unroll
    for (int p = 0; p < 4; ++p) {
        int pos = bstart[bs[p]] + hist[bs[p]][p * 32 + warp] + lr[p];
        float x = xs[p], y = ys[p], z = zs[p];
        g_sorted[bt * N_SZ + pos] =
            make_float4(x, y, z, fmaf(x, x, fmaf(y, y, z * z)));
        g_sbucket[bt * N_SZ + pos] = bs[p];
    }
}

// ---------------- main: windowed KNN + loss ---------------------------------
__global__ __launch_bounds__(MTHREADS)
void repulsion_grid_kernel(float* __restrict__ out) {
    __shared__ float wsum[MTHREADS / 32];
    __shared__ int   is_last;

    const int g     = blockIdx.x * MTHREADS + threadIdx.x;
    const int s     = g >> 1;                  // global sorted position
    const int split = g & 1;
    const int bt    = s >> 12;
    const int tid   = threadIdx.x;

    float4 q = g_sorted[s];
    const float m2x = -2.0f * q.x, m2y = -2.0f * q.y, m2z = -2.0f * q.z;
    const float qsq = q.w;

    const int  b   = g_sbucket[s];
    const int* bst = g_bstart + bt * (NB + 1);
    const int  lo  = bst[max(b - 1, 0)] + (bt << 12);
    const int  hi  = bst[min(b + 2, NB)] + (bt << 12);
    const int  mid = (lo + hi) >> 1;
    const int  beg = split ? mid : lo;
    const int  end = split ? hi  : mid;

    float d0 = FLT_MAX, d1 = FLT_MAX, d2 = FLT_MAX, d3 = FLT_MAX, d4 = FLT_MAX;

    for (int i = beg; i < end; i += 4) {
        float4 p0 = g_sorted[i];
        float4 p1 = g_sorted[i + 1];
        float4 p2 = g_sorted[i + 2];
        float4 p3 = g_sorted[i + 3];
        float va = fmaf(p0.x, m2x, fmaf(p0.y, m2y, fmaf(p0.z, m2z, p0.w)));
        float vb = fmaf(p1.x, m2x, fmaf(p1.y, m2y, fmaf(p1.z, m2z, p1.w)));
        float vc = fmaf(p2.x, m2x, fmaf(p2.y, m2y, fmaf(p2.z, m2z, p2.w)));
        float vd = fmaf(p3.x, m2x, fmaf(p3.y, m2y, fmaf(p3.z, m2z, p3.w)));
        vb = (i + 1 < end) ? vb : FLT_MAX;     // tail guard (discards garbage)
        vc = (i + 2 < end) ? vc : FLT_MAX;
        vd = (i + 3 < end) ? vd : FLT_MAX;
        CE(va, vb) CE(vc, vd) CE(va, vc) CE(vb, vd) CE(vb, vc)
        d1 = fminf(d1, vd); d2 = fminf(d2, vc);
        d3 = fminf(d3, vb); d4 = fminf(d4, va);
        CE(d0, d4) CE(d1, d3) CE(d2, d4) CE(d1, d2) CE(d3, d4)
    }

    // Merge the two splits of this query (lane pairs 2k, 2k+1).
    {
        float o0 = __shfl_xor_sync(FULL, d0, 1);
        float o1 = __shfl_xor_sync(FULL, d1, 1);
        float o2 = __shfl_xor_sync(FULL, d2, 1);
        float o3 = __shfl_xor_sync(FULL, d3, 1);
        float o4 = __shfl_xor_sync(FULL, d4, 1);
        ins5(d0, d1, d2, d3, d4, o0);
        ins5(d0, d1, d2, d3, d4, o1);
        ins5(d0, d1, d2, d3, d4, o2);
        ins5(d0, d1, d2, d3, d4, o3);
        ins5(d0, d1, d2, d3, d4, o4);
    }

    float loss = 0.0f;
    if (split == 0) {
        const float inv = -1.0f / H2;
        float t;
        t = fmaxf(d1 + qsq, 0.0f); loss -= t * expf(t * inv);
        t = fmaxf(d2 + qsq, 0.0f); loss -= t * expf(t * inv);
        t = fmaxf(d3 + qsq, 0.0f); loss -= t * expf(t * inv);
        t = fmaxf(d4 + qsq, 0.0f); loss -= t * expf(t * inv);
    }

    // Deterministic in-block reduction.
    #pragma unroll
    for (int o = 16; o > 0; o >>= 1)
        loss += __shfl_down_sync(FULL, loss, o);
    if ((tid & 31) == 0) wsum[tid >> 5] = loss;
    __syncthreads();

    if (tid == 0) {
        float acc = 0.0f;
        #pragma unroll
        for (int w = 0; w < MTHREADS / 32; ++w) acc += wsum[w];
        g_partial[blockIdx.x] = acc;
        __threadfence();
        int n = atomicAdd(&g_done, 1);
        is_last = (n == MGRID - 1);
    }
    __syncthreads();

    if (is_last) {
        __threadfence();
        float v = 0.0f;
        for (int i = tid; i < MGRID; i += MTHREADS) v += g_partial[i];
        #pragma unroll
        for (int o = 16; o > 0; o >>= 1)
            v += __shfl_down_sync(FULL, v, o);
        if ((tid & 31) == 0) wsum[tid >> 5] = v;
        __syncthreads();
        if (tid == 0) {
            float acc = 0.0f;
            #pragma unroll
            for (int w = 0; w < MTHREADS / 32; ++w) acc += wsum[w];
            out[0] = acc;
            g_done = 0;                        // reset for next graph replay
        }
    }
}

extern "C" void kernel_launch(void* const* d_in, const int* in_sizes, int n_in,
                              void* d_out, int out_size) {
    const float* pc = (const float*)d_in[0];
    build_kernel<<<B_SZ, 1024>>>(pc);
    repulsion_grid_kernel<<<MGRID, MTHREADS>>>((float*)d_out);
}

// round 8
// speedup vs baseline: 1.4608x; 1.0753x over previous
#include <cuda_runtime.h>
#include <math.h>
#include <float.h>

// RepulsionLoss: B=8, N=4096, KNN=4, H=0.03
// 2D grid pruning: weight exp(-d/H^2) makes any neighbor with max(|dx|,|dy|)
// >= 0.15 contribute <= e^-25 each (negligible vs fp32 loss). Bin points into
// 64x64 cells (width 0.15) with a stable two-pass counting sort (by y-cell,
// then x-cell); each query scans its 3x3 cell window (~66 candidates) as 3
// contiguous sorted ranges. Branch-free batched top-5 selection; self is the
// strict minimum -> slot 0, dropped (ref: top_k(KNN+1)-drop-first).
// Fully deterministic: stable sort, fixed scan order, fixed reduction order.

#define B_SZ     8
#define N_SZ     4096
#define ND       64
#define NCELL    (ND * ND)
#define WID      0.15f
#define X0       (-4.8f)
#define INVW     (1.0f / WID)
#define H2       (0.03f * 0.03f)
#define FULL     0xffffffffu

#define GTHREADS 256
#define GGRID    ((B_SZ * N_SZ) / GTHREADS)   // 128 blocks

__device__ float4 g_tmp[B_SZ * N_SZ];          // pass-1 sorted points
__device__ int    g_tmpc[B_SZ * N_SZ];         // pass-1 sorted cell ids
__device__ float4 g_sorted[B_SZ * N_SZ + 4];   // final sorted (+pad, .bss=0)
__device__ int    g_scell[B_SZ * N_SZ];
__device__ int    g_cst[B_SZ * (NCELL + 1)];   // per-batch cell starts
__device__ float  g_partial[GGRID];
__device__ int    g_done;                       // zero-init; self-resetting

#define CE(x, y) { float t_ = fminf((x), (y)); (y) = fmaxf((x), (y)); (x) = t_; }

// ---------------- build: fused 2-pass stable counting sort ------------------
__global__ __launch_bounds__(1024)
void build_kernel(const float* __restrict__ pc) {
    __shared__ int hist[ND][128];      // [bucket][pass*32 + warp]
    __shared__ int btot[ND];
    __shared__ int bst[ND + 1];

    const int tid  = threadIdx.x;
    const int bt   = blockIdx.x;
    const int warp = tid >> 5;
    const int lane = tid & 31;
    const unsigned lmask = (1u << lane) - 1u;

    // ---- pass 1: stable sort by y-cell ----
    for (int i = tid; i < ND * 128; i += 1024) (&hist[0][0])[i] = 0;
    __syncthreads();

    float4 pt[4]; int cell[4], key[4], lr[4];
    #pragma unroll
    for (int p = 0; p < 4; ++p) {
        int i = p * 1024 + tid;
        const float* s = pc + ((size_t)bt * N_SZ + i) * 3;
        float x = s[0], y = s[1], z = s[2];
        int bx = min(ND - 1, max(0, (int)((x - X0) * INVW)));
        int by = min(ND - 1, max(0, (int)((y - X0) * INVW)));
        pt[p]   = make_float4(x, y, z, fmaf(x, x, fmaf(y, y, z * z)));
        cell[p] = bx * ND + by;
        key[p]  = by;
        unsigned m = __match_any_sync(FULL, by);
        lr[p] = __popc(m & lmask);
        if ((__ffs(m) - 1) == lane) hist[by][p * 32 + warp] = __popc(m);
    }
    __syncthreads();
    if (tid < ND) {
        int a = 0;
        for (int s = 0; s < 128; ++s) { int c = hist[tid][s]; hist[tid][s] = a; a += c; }
        btot[tid] = a;
    }
    __syncthreads();
    if (tid == 0) {
        int a = 0;
        for (int b = 0; b < ND; ++b) { bst[b] = a; a += btot[b]; }
        bst[ND] = a;
    }
    __syncthreads();
    #pragma unroll
    for (int p = 0; p < 4; ++p) {
        int pos = bst[key[p]] + hist[key[p]][p * 32 + warp] + lr[p];
        g_tmp[bt * N_SZ + pos]  = pt[p];
        g_tmpc[bt * N_SZ + pos] = cell[p];
    }
    __syncthreads();

    // ---- pass 2: stable sort by x-cell (final order = cell id ascending) ----
    for (int i = tid; i < ND * 128; i += 1024) (&hist[0][0])[i] = 0;
    __syncthreads();
    #pragma unroll
    for (int p = 0; p < 4; ++p) {
        int i = p * 1024 + tid;
        pt[p]   = g_tmp[bt * N_SZ + i];
        cell[p] = g_tmpc[bt * N_SZ + i];
        key[p]  = cell[p] >> 6;                    // bx
        unsigned m = __match_any_sync(FULL, key[p]);
        lr[p] = __popc(m & lmask);
        if ((__ffs(m) - 1) == lane) hist[key[p]][p * 32 + warp] = __popc(m);
    }
    __syncthreads();
    if (tid < ND) {
        int a = 0;
        for (int s = 0; s < 128; ++s) { int c = hist[tid][s]; hist[tid][s] = a; a += c; }
        btot[tid] = a;
    }
    __syncthreads();
    if (tid == 0) {
        int a = 0;
        for (int b = 0; b < ND; ++b) { bst[b] = a; a += btot[b]; }
        bst[ND] = a;
    }
    __syncthreads();
    #pragma unroll
    for (int p = 0; p < 4; ++p) {
        int pos = bst[key[p]] + hist[key[p]][p * 32 + warp] + lr[p];
        g_sorted[bt * N_SZ + pos] = pt[p];
        g_scell[bt * N_SZ + pos]  = cell[p];
    }
    __syncthreads();

    // ---- cell-start table (boundary fill over sorted cell ids) ----
    int* cst = g_cst + bt * (NCELL + 1);
    #pragma unroll
    for (int p = 0; p < 4; ++p) {
        int i  = p * 1024 + tid;
        int c  = g_scell[bt * N_SZ + i];
        int cp = (i == 0) ? -1 : g_scell[bt * N_SZ + i - 1];
        for (int cc = cp + 1; cc <= c; ++cc) cst[cc] = i;
        if (i == N_SZ - 1)
            for (int cc = c + 1; cc <= NCELL; ++cc) cst[cc] = N_SZ;
    }
}

// ---------------- main: 3x3-window KNN + loss -------------------------------
__global__ __launch_bounds__(GTHREADS)
void repulsion_grid_kernel(float* __restrict__ out) {
    __shared__ float wsum[GTHREADS / 32];
    __shared__ int   is_last;

    const int s   = blockIdx.x * GTHREADS + threadIdx.x;   // sorted query pos
    const int bt  = s >> 12;
    const int tid = threadIdx.x;

    float4 q = g_sorted[s];
    const float m2x = -2.0f * q.x, m2y = -2.0f * q.y, m2z = -2.0f * q.z;
    const float qsq = q.w;

    const int  cell = g_scell[s];
    const int  bx = cell >> 6, by = cell & (ND - 1);
    const int* cst = g_cst + bt * (NCELL + 1);
    const int  rlo  = max(by - 1, 0);
    const int  rhi  = min(by + 2, ND);
    const int  cxlo = max(bx - 1, 0);
    const int  cxhi = min(bx + 1, ND - 1);
    const int  bbase = bt << 12;

    float d0 = FLT_MAX, d1 = FLT_MAX, d2 = FLT_MAX, d3 = FLT_MAX, d4 = FLT_MAX;

    for (int cx = cxlo; cx <= cxhi; ++cx) {
        const int lo = cst[cx * ND + rlo] + bbase;
        const int hi = cst[cx * ND + rhi] + bbase;
        for (int i = lo; i < hi; i += 4) {
            float4 p0 = g_sorted[i];
            float4 p1 = g_sorted[i + 1];
            float4 p2 = g_sorted[i + 2];
            float4 p3 = g_sorted[i + 3];
            float va = fmaf(p0.x, m2x, fmaf(p0.y, m2y, fmaf(p0.z, m2z, p0.w)));
            float vb = fmaf(p1.x, m2x, fmaf(p1.y, m2y, fmaf(p1.z, m2z, p1.w)));
            float vc = fmaf(p2.x, m2x, fmaf(p2.y, m2y, fmaf(p2.z, m2z, p2.w)));
            float vd = fmaf(p3.x, m2x, fmaf(p3.y, m2y, fmaf(p3.z, m2z, p3.w)));
            vb = (i + 1 < hi) ? vb : FLT_MAX;    // tail guards
            vc = (i + 2 < hi) ? vc : FLT_MAX;
            vd = (i + 3 < hi) ? vd : FLT_MAX;
            CE(va, vb) CE(vc, vd) CE(va, vc) CE(vb, vd) CE(vb, vc)
            d1 = fminf(d1, vd); d2 = fminf(d2, vc);
            d3 = fminf(d3, vb); d4 = fminf(d4, va);
            CE(d0, d4) CE(d1, d3) CE(d2, d4) CE(d1, d2) CE(d3, d4)
        }
    }

    const float inv = -1.0f / H2;
    float loss = 0.0f, t;
    t = fmaxf(d1 + qsq, 0.0f); loss -= t * expf(t * inv);
    t = fmaxf(d2 + qsq, 0.0f); loss -= t * expf(t * inv);
    t = fmaxf(d3 + qsq, 0.0f); loss -= t * expf(t * inv);
    t = fmaxf(d4 + qsq, 0.0f); loss -= t * expf(t * inv);

    // Deterministic in-block reduction.
    #pragma unroll
    for (int o = 16; o > 0; o >>= 1)
        loss += __shfl_down_sync(FULL, loss, o);
    if ((tid & 31) == 0) wsum[tid >> 5] = loss;
    __syncthreads();

    if (tid == 0) {
        float acc = 0.0f;
        #pragma unroll
        for (int w = 0; w < GTHREADS / 32; ++w) acc += wsum[w];
        g_partial[blockIdx.x] = acc;
        __threadfence();
        int n = atomicAdd(&g_done, 1);
        is_last = (n == GGRID - 1);
    }
    __syncthreads();

    if (is_last) {
        __threadfence();
        float v = (tid < GGRID) ? g_partial[tid] : 0.0f;
        #pragma unroll
        for (int o = 16; o > 0; o >>= 1)
            v += __shfl_down_sync(FULL, v, o);
        if ((tid & 31) == 0) wsum[tid >> 5] = v;
        __syncthreads();
        if (tid == 0) {
            float acc = 0.0f;
            #pragma unroll
            for (int w = 0; w < GTHREADS / 32; ++w) acc += wsum[w];
            out[0] = acc;
            g_done = 0;                        // reset for next graph replay
        }
    }
}

extern "C" void kernel_launch(void* const* d_in, const int* in_sizes, int n_in,
                              void* d_out, int out_size) {
    const float* pc = (const float*)d_in[0];
    build_kernel<<<B_SZ, 1024>>>(pc);
    repulsion_grid_kernel<<<GGRID, GTHREADS>>>((float*)d_out);
}

// round 9
// speedup vs baseline: 2.1097x; 1.4442x over previous
#include <cuda_runtime.h>
#include <math.h>
#include <float.h>

// RepulsionLoss: B=8, N=4096, KNN=4, H=0.03
// 2D grid pruning (64x64 cells, width 0.15): any neighbor outside the 3x3
// cell window has d^2 >= 0.0225 -> weight <= e^-25, negligible. Stable
// two-pass counting sort (y-cell then x-cell) with warp-parallel shfl scans;
// each query scans its 3x3 window (~66 candidates) as 3 contiguous ranges,
// split across 2 threads and shfl-merged. Branch-free batched top-5; self is
// the strict min -> slot 0, dropped (ref: top_k(KNN+1)-drop-first).
// Fully deterministic: stable sort, fixed scan & reduction order.

#define B_SZ     8
#define N_SZ     4096
#define ND       64
#define NCELL    (ND * ND)
#define WID      0.15f
#define X0       (-4.8f)
#define INVW     (1.0f / WID)
#define H2       (0.03f * 0.03f)
#define FULL     0xffffffffu

#define GTHREADS 256
#define GGRID    ((B_SZ * N_SZ * 2) / GTHREADS)   // 256 blocks, 2 splits/query

__device__ float4 g_tmp[B_SZ * N_SZ];
__device__ int    g_tmpc[B_SZ * N_SZ];
__device__ float4 g_sorted[B_SZ * N_SZ + 4];   // +pad (.bss zeros)
__device__ int    g_scell[B_SZ * N_SZ];
__device__ int    g_cst[B_SZ * (NCELL + 1)];
__device__ float  g_partial[GGRID];
__device__ int    g_done;                       // zero-init; self-resetting

#define CE(x, y) { float t_ = fminf((x), (y)); (y) = fmaxf((x), (y)); (x) = t_; }

__device__ __forceinline__ void ins5(float& d0, float& d1, float& d2,
                                     float& d3, float& d4, float v) {
    d4 = fminf(d4, v);
    CE(d3, d4) CE(d2, d3) CE(d1, d2) CE(d0, d1)
}

// ---------------- build: fused 2-pass stable counting sort ------------------
__global__ __launch_bounds__(1024)
void build_kernel(const float* __restrict__ pc) {
    __shared__ int hist[ND][128];      // [bucket][pass*32 + warp]
    __shared__ int btot[ND];
    __shared__ int bst[ND + 1];

    const int tid  = threadIdx.x;
    const int bt   = blockIdx.x;
    const int warp = tid >> 5;
    const int lane = tid & 31;
    const unsigned lmask = (1u << lane) - 1u;

    float4 pt[4]; int cell[4], key[4], lr[4];

    #pragma unroll
    for (int pass = 0; pass < 2; ++pass) {
        for (int i = tid; i < ND * 128; i += 1024) (&hist[0][0])[i] = 0;
        __syncthreads();

        #pragma unroll
        for (int p = 0; p < 4; ++p) {
            int i = p * 1024 + tid;
            if (pass == 0) {
                const float* s = pc + ((size_t)bt * N_SZ + i) * 3;
                float x = s[0], y = s[1], z = s[2];
                int bx = min(ND - 1, max(0, (int)((x - X0) * INVW)));
                int by = min(ND - 1, max(0, (int)((y - X0) * INVW)));
                pt[p]   = make_float4(x, y, z, fmaf(x, x, fmaf(y, y, z * z)));
                cell[p] = bx * ND + by;
                key[p]  = by;
            } else {
                pt[p]   = g_tmp[bt * N_SZ + i];
                cell[p] = g_tmpc[bt * N_SZ + i];
                key[p]  = cell[p] >> 6;                  // bx
            }
            unsigned m = __match_any_sync(FULL, key[p]);
            lr[p] = __popc(m & lmask);
            if ((__ffs(m) - 1) == lane) hist[key[p]][p * 32 + warp] = __popc(m);
        }
        __syncthreads();

        // Warp-parallel exclusive scan of each bucket's 128 slots.
        #pragma unroll
        for (int r = 0; r < 2; ++r) {
            int bkt = warp * 2 + r;
            int off = 0;
            #pragma unroll
            for (int c = 0; c < 4; ++c) {
                int orig = hist[bkt][c * 32 + lane];
                int v = orig;
                #pragma unroll
                for (int o = 1; o < 32; o <<= 1) {
                    int n = __shfl_up_sync(FULL, v, o);
                    if (lane >= o) v += n;
                }
                hist[bkt][c * 32 + lane] = off + v - orig;
                off += __shfl_sync(FULL, v, 31);
            }
            if (lane == 0) btot[bkt] = off;
        }
        __syncthreads();

        // Exclusive scan of the 64 bucket totals (warp 0, shfl).
        if (warp == 0) {
            int v0 = btot[lane];
            int v1 = btot[32 + lane];
            int s0 = v0, s1 = v1;
            #pragma unroll
            for (int o = 1; o < 32; o <<= 1) {
                int n0 = __shfl_up_sync(FULL, s0, o);
                int n1 = __shfl_up_sync(FULL, s1, o);
                if (lane >= o) { s0 += n0; s1 += n1; }
            }
            int tot0 = __shfl_sync(FULL, s0, 31);
            bst[lane]      = s0 - v0;
            bst[32 + lane] = tot0 + s1 - v1;
            if (lane == 31) bst[ND] = tot0 + s1;       // == N_SZ
        }
        __syncthreads();

        #pragma unroll
        for (int p = 0; p < 4; ++p) {
            int pos = bst[key[p]] + hist[key[p]][p * 32 + warp] + lr[p];
            if (pass == 0) {
                g_tmp[bt * N_SZ + pos]  = pt[p];
                g_tmpc[bt * N_SZ + pos] = cell[p];
            } else {
                g_sorted[bt * N_SZ + pos] = pt[p];
                g_scell[bt * N_SZ + pos]  = cell[p];
            }
        }
        __syncthreads();
    }

    // Cell-start table (boundary fill over sorted cell ids).
    int* cst = g_cst + bt * (NCELL + 1);
    #pragma unroll
    for (int p = 0; p < 4; ++p) {
        int i  = p * 1024 + tid;
        int c  = g_scell[bt * N_SZ + i];
        int cp = (i == 0) ? -1 : g_scell[bt * N_SZ + i - 1];
        for (int cc = cp + 1; cc <= c; ++cc) cst[cc] = i;
        if (i == N_SZ - 1)
            for (int cc = c + 1; cc <= NCELL; ++cc) cst[cc] = N_SZ;
    }
}

// ---------------- main: 3x3-window KNN + loss (2 splits/query) --------------
__global__ __launch_bounds__(GTHREADS)
void repulsion_grid_kernel(float* __restrict__ out) {
    __shared__ float wsum[GTHREADS / 32];
    __shared__ int   is_last;

    const int g     = blockIdx.x * GTHREADS + threadIdx.x;
    const int s     = g >> 1;                  // sorted query position
    const int split = g & 1;
    const int bt    = s >> 12;
    const int tid   = threadIdx.x;

    float4 q = g_sorted[s];
    const float m2x = -2.0f * q.x, m2y = -2.0f * q.y, m2z = -2.0f * q.z;
    const float qsq = q.w;

    const int  cell = g_scell[s];
    const int  bx = cell >> 6, by = cell & (ND - 1);
    const int* cst = g_cst + bt * (NCELL + 1);
    const int  rlo  = max(by - 1, 0);
    const int  rhi  = min(by + 2, ND);
    const int  cxlo = max(bx - 1, 0);
    const int  cxhi = min(bx + 1, ND - 1);
    const int  bbase = bt << 12;

    float d0 = FLT_MAX, d1 = FLT_MAX, d2 = FLT_MAX, d3 = FLT_MAX, d4 = FLT_MAX;

    for (int cx = cxlo; cx <= cxhi; ++cx) {
        const int clo = cst[cx * ND + rlo] + bbase;
        const int chi = cst[cx * ND + rhi] + bbase;
        const int cmid = (clo + chi) >> 1;
        const int lo = split ? cmid : clo;
        const int hi = split ? chi  : cmid;
        for (int i = lo; i < hi; i += 4) {
            float4 p0 = g_sorted[i];
            float4 p1 = g_sorted[i + 1];
            float4 p2 = g_sorted[i + 2];
            float4 p3 = g_sorted[i + 3];
            float va = fmaf(p0.x, m2x, fmaf(p0.y, m2y, fmaf(p0.z, m2z, p0.w)));
            float vb = fmaf(p1.x, m2x, fmaf(p1.y, m2y, fmaf(p1.z, m2z, p1.w)));
            float vc = fmaf(p2.x, m2x, fmaf(p2.y, m2y, fmaf(p2.z, m2z, p2.w)));
            float vd = fmaf(p3.x, m2x, fmaf(p3.y, m2y, fmaf(p3.z, m2z, p3.w)));
            vb = (i + 1 < hi) ? vb : FLT_MAX;   // tail guards
            vc = (i + 2 < hi) ? vc : FLT_MAX;
            vd = (i + 3 < hi) ? vd : FLT_MAX;
            CE(va, vb) CE(vc, vd) CE(va, vc) CE(vb, vd) CE(vb, vc)
            d1 = fminf(d1, vd); d2 = fminf(d2, vc);
            d3 = fminf(d3, vb); d4 = fminf(d4, va);
            CE(d0, d4) CE(d1, d3) CE(d2, d4) CE(d1, d2) CE(d3, d4)
        }
    }

    // Merge the two splits of this query (lane pairs 2k, 2k+1).
    {
        float o0 = __shfl_xor_sync(FULL, d0, 1);
        float o1 = __shfl_xor_sync(FULL, d1, 1);
        float o2 = __shfl_xor_sync(FULL, d2, 1);
        float o3 = __shfl_xor_sync(FULL, d3, 1);
        float o4 = __shfl_xor_sync(FULL, d4, 1);
        ins5(d0, d1, d2, d3, d4, o0);
        ins5(d0, d1, d2, d3, d4, o1);
        ins5(d0, d1, d2, d3, d4, o2);
        ins5(d0, d1, d2, d3, d4, o3);
        ins5(d0, d1, d2, d3, d4, o4);
    }

    float loss = 0.0f;
    if (split == 0) {
        const float inv = -1.0f / H2;
        float t;
        t = fmaxf(d1 + qsq, 0.0f); loss -= t * expf(t * inv);
        t = fmaxf(d2 + qsq, 0.0f); loss -= t * expf(t * inv);
        t = fmaxf(d3 + qsq, 0.0f); loss -= t * expf(t * inv);
        t = fmaxf(d4 + qsq, 0.0f); loss -= t * expf(t * inv);
    }

    // Deterministic in-block reduction.
    #pragma unroll
    for (int o = 16; o > 0; o >>= 1)
        loss += __shfl_down_sync(FULL, loss, o);
    if ((tid & 31) == 0) wsum[tid >> 5] = loss;
    __syncthreads();

    if (tid == 0) {
        float acc = 0.0f;
        #pragma unroll
        for (int w = 0; w < GTHREADS / 32; ++w) acc += wsum[w];
        g_partial[blockIdx.x] = acc;
        __threadfence();
        int n = atomicAdd(&g_done, 1);
        is_last = (n == GGRID - 1);
    }
    __syncthreads();

    if (is_last) {
        __threadfence();
        float v = (tid < GGRID) ? g_partial[tid] : 0.0f;
        #pragma unroll
        for (int o = 16; o > 0; o >>= 1)
            v += __shfl_down_sync(FULL, v, o);
        if ((tid & 31) == 0) wsum[tid >> 5] = v;
        __syncthreads();
        if (tid == 0) {
            float acc = 0.0f;
            #pragma unroll
            for (int w = 0; w < GTHREADS / 32; ++w) acc += wsum[w];
            out[0] = acc;
            g_done = 0;                        // reset for next graph replay
        }
    }
}

extern "C" void kernel_launch(void* const* d_in, const int* in_sizes, int n_in,
                              void* d_out, int out_size) {
    const float* pc = (const float*)d_in[0];
    build_kernel<<<B_SZ, 1024>>>(pc);
    repulsion_grid_kernel<<<GGRID, GTHREADS>>>((float*)d_out);
}

// round 10
// speedup vs baseline: 3.2319x; 1.5319x over previous
#include <cuda_runtime.h>
#include <math.h>
#include <float.h>

// RepulsionLoss: B=8, N=4096, KNN=4, H=0.03
// 2D grid pruning (64x64 cells, width 0.15): neighbors outside the 3x3 cell
// window have d^2 >= 0.0225 -> weight <= e^-25, negligible. Build = unordered
// counting sort by cell (atomic ranks; counts & cell starts deterministic).
// Per-query loss comes from the 5 smallest distances via an exact min/max
// network -> invariant to candidate order, so within-cell order freedom is
// harmless; losses are scattered to ORIGINAL point indices and reduced in
// fixed order -> deterministic output. Self is the strict min -> slot 0,
// dropped (matches reference top_k(KNN+1)-drop-first).

#define B_SZ     8
#define N_SZ     4096
#define NPTS     (B_SZ * N_SZ)
#define ND       64
#define NCELL    (ND * ND)
#define WID      0.15f
#define X0       (-4.8f)
#define INVW     (1.0f / WID)
#define H2       (0.03f * 0.03f)
#define FULL     0xffffffffu

#define STHREADS 256
#define SGRID    ((NPTS * 4) / STHREADS)     // 512 blocks, 4 splits/query

__device__ float4 g_aug[NPTS];               // (x,y,z,|p|^2) original order
__device__ int    g_cell[NPTS];
__device__ int    g_rank[NPTS];
__device__ int    g_cnt[B_SZ * NCELL];       // zero-init; self-resetting (K2)
__device__ float4 g_sorted[NPTS + 4];        // +pad (.bss zeros)
__device__ int    g_scell[NPTS];
__device__ int    g_sidx[NPTS];              // sorted pos -> original index
__device__ float  g_loss[NPTS];
__device__ int    g_done;                    // zero-init; self-resetting

#define CE(x, y) { float t_ = fminf((x), (y)); (y) = fmaxf((x), (y)); (x) = t_; }

__device__ __forceinline__ void ins5(float& d0, float& d1, float& d2,
                                     float& d3, float& d4, float v) {
    d4 = fminf(d4, v);
    CE(d3, d4) CE(d2, d3) CE(d1, d2) CE(d0, d1)
}

// K1: cells + atomic ranks + augmented points (32 blocks, full chip).
__global__ __launch_bounds__(1024)
void prep_kernel(const float* __restrict__ pc) {
    const int i  = blockIdx.x * 1024 + threadIdx.x;     // 0..NPTS-1
    const int bt = i >> 12;
    const float* s = pc + (size_t)i * 3;
    float x = s[0], y = s[1], z = s[2];
    int bx = min(ND - 1, max(0, (int)((x - X0) * INVW)));
    int by = min(ND - 1, max(0, (int)((y - X0) * INVW)));
    int cell = bx * ND + by;
    g_aug[i]  = make_float4(x, y, z, fmaf(x, x, fmaf(y, y, z * z)));
    g_cell[i] = cell;
    g_rank[i] = atomicAdd(&g_cnt[bt * NCELL + cell], 1);
}

// K2: per-batch exclusive scan of 4096 bins -> g_cst; resets g_cnt.
__device__ int g_cst[B_SZ * (NCELL + 1)];

__global__ __launch_bounds__(1024)
void scan_kernel() {
    __shared__ int wtot[32];
    __shared__ int wpre[32];
    const int tid  = threadIdx.x;
    const int bt   = blockIdx.x;
    const int warp = tid >> 5;
    const int lane = tid & 31;

    int* cnt = g_cnt + bt * NCELL;
    int  c0 = cnt[tid * 4 + 0], c1 = cnt[tid * 4 + 1];
    int  c2 = cnt[tid * 4 + 2], c3 = cnt[tid * 4 + 3];
    cnt[tid * 4 + 0] = 0; cnt[tid * 4 + 1] = 0;          // reset for next replay
    cnt[tid * 4 + 2] = 0; cnt[tid * 4 + 3] = 0;

    int tsum = c0 + c1 + c2 + c3;
    int incl = tsum;
    #pragma unroll
    for (int o = 1; o < 32; o <<= 1) {
        int n = __shfl_up_sync(FULL, incl, o);
        if (lane >= o) incl += n;
    }
    if (lane == 31) wtot[warp] = incl;
    __syncthreads();
    if (warp == 0) {
        int v = wtot[lane], sincl = v;
        #pragma unroll
        for (int o = 1; o < 32; o <<= 1) {
            int n = __shfl_up_sync(FULL, sincl, o);
            if (lane >= o) sincl += n;
        }
        wpre[lane] = sincl - v;
    }
    __syncthreads();

    int base = wpre[warp] + (incl - tsum);
    int* cst = g_cst + bt * (NCELL + 1);
    cst[tid * 4 + 0] = base;
    cst[tid * 4 + 1] = base + c0;
    cst[tid * 4 + 2] = base + c0 + c1;
    cst[tid * 4 + 3] = base + c0 + c1 + c2;
    if (tid == 0) cst[NCELL] = N_SZ;
}

// K3: scatter points into cell order.
__global__ __launch_bounds__(1024)
void scatter_kernel() {
    const int i  = blockIdx.x * 1024 + threadIdx.x;
    const int bt = i >> 12;
    int cell = g_cell[i];
    int pos  = bt * N_SZ + g_cst[bt * (NCELL + 1) + cell] + g_rank[i];
    g_sorted[pos] = g_aug[i];
    g_scell[pos]  = cell;
    g_sidx[pos]   = i;
}

// K4: 3x3-window KNN + loss (4 splits/query) + fused deterministic reduce.
__global__ __launch_bounds__(STHREADS)
void repulsion_grid_kernel(float* __restrict__ out) {
    __shared__ float wsum[STHREADS / 32];
    __shared__ int   is_last;

    const int g     = blockIdx.x * STHREADS + threadIdx.x;
    const int s     = g >> 2;                  // sorted query position
    const int split = g & 3;
    const int bt    = s >> 12;
    const int tid   = threadIdx.x;

    float4 q = g_sorted[s];
    const float m2x = -2.0f * q.x, m2y = -2.0f * q.y, m2z = -2.0f * q.z;
    const float qsq = q.w;

    const int  cell = g_scell[s];
    const int  bx = cell >> 6, by = cell & (ND - 1);
    const int* cst = g_cst + bt * (NCELL + 1);
    const int  rlo  = max(by - 1, 0);
    const int  rhi  = min(by + 2, ND);
    const int  cxlo = max(bx - 1, 0);
    const int  cxhi = min(bx + 1, ND - 1);
    const int  bbase = bt << 12;

    float d0 = FLT_MAX, d1 = FLT_MAX, d2 = FLT_MAX, d3 = FLT_MAX, d4 = FLT_MAX;

    for (int cx = cxlo; cx <= cxhi; ++cx) {
        const int clo = cst[cx * ND + rlo] + bbase;
        const int chi = cst[cx * ND + rhi] + bbase;
        const int len = chi - clo;
        const int lo  = clo + ((len * split) >> 2);
        const int hi  = clo + ((len * (split + 1)) >> 2);
        for (int i = lo; i < hi; i += 4) {
            float4 p0 = g_sorted[i];
            float4 p1 = g_sorted[i + 1];
            float4 p2 = g_sorted[i + 2];
            float4 p3 = g_sorted[i + 3];
            float va = fmaf(p0.x, m2x, fmaf(p0.y, m2y, fmaf(p0.z, m2z, p0.w)));
            float vb = fmaf(p1.x, m2x, fmaf(p1.y, m2y, fmaf(p1.z, m2z, p1.w)));
            float vc = fmaf(p2.x, m2x, fmaf(p2.y, m2y, fmaf(p2.z, m2z, p2.w)));
            float vd = fmaf(p3.x, m2x, fmaf(p3.y, m2y, fmaf(p3.z, m2z, p3.w)));
            vb = (i + 1 < hi) ? vb : FLT_MAX;   // tail guards
            vc = (i + 2 < hi) ? vc : FLT_MAX;
            vd = (i + 3 < hi) ? vd : FLT_MAX;
            CE(va, vb) CE(vc, vd) CE(va, vc) CE(vb, vd) CE(vb, vc)
            d1 = fminf(d1, vd); d2 = fminf(d2, vc);
            d3 = fminf(d3, vb); d4 = fminf(d4, va);
            CE(d0, d4) CE(d1, d3) CE(d2, d4) CE(d1, d2) CE(d3, d4)
        }
    }

    // Butterfly merge of the 4 splits (lanes 4k..4k+3 share a query).
    #pragma unroll
    for (int x = 1; x <= 2; x <<= 1) {
        float o0 = __shfl_xor_sync(FULL, d0, x);
        float o1 = __shfl_xor_sync(FULL, d1, x);
        float o2 = __shfl_xor_sync(FULL, d2, x);
        float o3 = __shfl_xor_sync(FULL, d3, x);
        float o4 = __shfl_xor_sync(FULL, d4, x);
        ins5(d0, d1, d2, d3, d4, o0);
        ins5(d0, d1, d2, d3, d4, o1);
        ins5(d0, d1, d2, d3, d4, o2);
        ins5(d0, d1, d2, d3, d4, o3);
        ins5(d0, d1, d2, d3, d4, o4);
    }

    if (split == 0) {
        const float inv = -1.0f / H2;
        float loss = 0.0f, t;
        t = fmaxf(d1 + qsq, 0.0f); loss -= t * expf(t * inv);
        t = fmaxf(d2 + qsq, 0.0f); loss -= t * expf(t * inv);
        t = fmaxf(d3 + qsq, 0.0f); loss -= t * expf(t * inv);
        t = fmaxf(d4 + qsq, 0.0f); loss -= t * expf(t * inv);
        g_loss[g_sidx[s]] = loss;              // order-invariant value
    }

    __threadfence();                           // publish g_loss writes
    __syncthreads();
    if (tid == 0) {
        int n = atomicAdd(&g_done, 1);
        is_last = (n == SGRID - 1);
    }
    __syncthreads();

    // Last block: deterministic fixed-order reduction over original indices.
    if (is_last) {
        __threadfence();
        const float4* lv = (const float4*)g_loss;
        float acc = 0.0f;
        #pragma unroll
        for (int j = 0; j < NPTS / 4 / STHREADS; ++j) {   // 32 float4s/thread
            float4 v = lv[j * STHREADS + tid];
            acc += (v.x + v.y) + (v.z + v.w);
        }
        #pragma unroll
        for (int o = 16; o > 0; o >>= 1)
            acc += __shfl_down_sync(FULL, acc, o);
        if ((tid & 31) == 0) wsum[tid >> 5] = acc;
        __syncthreads();
        if (tid == 0) {
            float t = 0.0f;
            #pragma unroll
            for (int w = 0; w < STHREADS / 32; ++w) t += wsum[w];
            out[0] = t;
            g_done = 0;                        // reset for next graph replay
        }
    }
}

extern "C" void kernel_launch(void* const* d_in, const int* in_sizes, int n_in,
                              void* d_out, int out_size) {
    const float* pc = (const float*)d_in[0];
    prep_kernel<<<NPTS / 1024, 1024>>>(pc);
    scan_kernel<<<B_SZ, 1024>>>();
    scatter_kernel<<<NPTS / 1024, 1024>>>();
    repulsion_grid_kernel<<<SGRID, STHREADS>>>((float*)d_out);
}